// round 15
// baseline (speedup 1.0000x reference)
#include <cuda_runtime.h>
#include <cuda_bf16.h>

#define NB 256
#define TLEN 1000
#define T2 1001

// ---------------- device scratch (static, allocation-free) ----------------
__device__ float g_W1f[22*22];
__device__ float g_b1f[22];
__device__ float g_W2f[25*22*12];
__device__ float g_b2f[25];
__device__ float g_sig[NB*25*T2];
__device__ float g_cov[NB*3*625];
__device__ float g_w[NB*3*30];
__device__ float g_logV[NB*3*30*625];   // weighted log(V_i), 57.6MB
__device__ float g_xm[NB*3*625];

// ---------------- helpers ----------------
__device__ __forceinline__ float warp_sum(float v){
    #pragma unroll
    for (int o=16;o;o>>=1) v += __shfl_xor_sync(0xffffffffu, v, o);
    return v;
}

__device__ __forceinline__ void sub_info(int i,int&k,int&r0,int&c0,int&g){
    if(i<16){g=0;k=2;r0=i>>2;c0=i&3;}
    else if(i<25){g=1;k=3;int s=i-16;r0=s/3;c0=s%3;}
    else if(i<29){g=2;k=4;int s=i-25;r0=s>>1;c0=s&1;}
    else{g=3;k=5;r0=0;c0=0;}
}

// triangular-index -> (r,c), r<=c
__device__ __forceinline__ void tri25(int e,int&r,int&c){
    int rr = (int)((51.f - sqrtf(2601.f - 8.f*(float)e)) * 0.5f);
    if (rr > 0 && (rr*(51-rr))/2 > e) rr--;
    while (((rr+1)*(50-rr))/2 <= e) rr++;
    r = rr;
    c = rr + (e - (rr*(51-rr))/2);
}
__device__ __forceinline__ void tri18(int e,int&r,int&c){
    int rr = (int)((37.f - sqrtf(1369.f - 8.f*(float)e)) * 0.5f);
    if (rr > 0 && (rr*(37-rr))/2 > e) rr--;
    while (((rr+1)*(36-rr))/2 <= e) rr++;
    r = rr;
    c = rr + (e - (rr*(37-rr))/2);
}

// ---------------- f32x2 packed helpers (sm_103a dual-FP32 path) ------------
__device__ __forceinline__ unsigned long long pk2(float lo, float hi){
    unsigned long long r;
    asm("mov.b64 %0,{%1,%2};" : "=l"(r) : "f"(lo), "f"(hi));
    return r;
}
__device__ __forceinline__ void upk2(unsigned long long v, float& lo, float& hi){
    asm("mov.b64 {%0,%1},%2;" : "=f"(lo), "=f"(hi) : "l"(v));
}
__device__ __forceinline__ unsigned long long fma2(unsigned long long a, unsigned long long b, unsigned long long c){
    unsigned long long d;
    asm("fma.rn.f32x2 %0, %1, %2, %3;" : "=l"(d) : "l"(a), "l"(b), "l"(c));
    return d;
}
__device__ __forceinline__ unsigned long long mul2(unsigned long long a, unsigned long long b){
    unsigned long long d;
    asm("mul.rn.f32x2 %0, %1, %2;" : "=l"(d) : "l"(a), "l"(b));
    return d;
}

// ---------------- one-sided (Hestenes) Jacobi, f32x2-packed columns --------
template<int N>
__device__ __forceinline__ void hestenes_p(unsigned long long (&ap)[(N+1)/2], float &x, int lane, int max_sweeps){
    constexpr int NP = (N + 1) / 2;
    constexpr int ROT = (N & 1) ? N : (N - 1);
    const unsigned FULL = 0xffffffffu;
    for (int sweep=0; sweep<max_sweeps; sweep++){
        int any=0;
        for (int r=0;r<ROT;r++){
            int partner;
            if (lane > ROT) partner = lane;
            else if (lane == ROT) partner = (ROT - r) % ROT;
            else {
                int pos = lane + r; if (pos >= ROT) pos -= ROT;
                if (pos == 0) partner = ROT;
                else { int pl = ROT - pos - r; if (pl < 0) pl += ROT; partner = pl; }
            }
            unsigned long long bp[NP];
            #pragma unroll
            for (int j=0;j<NP;j++) bp[j]=__shfl_sync(FULL,ap[j],partner);
            float y=__shfl_sync(FULL,x,partner);
            unsigned long long zacc = 0ull;
            #pragma unroll
            for (int j=0;j<NP;j++) zacc = fma2(ap[j], bp[j], zacc);
            float zlo, zhi; upk2(zacc, zlo, zhi);
            float z = zlo + zhi;
            if (lane<N && partner<N && z*z > 3e-8f*x*y + 1e-37f){
                any=1;
                bool up = lane<partner;
                float xp = up?x:y, xq = up?y:x;
                float tau = __fdividef(xq-xp, 2.f*z);
                float t = copysignf(1.f,tau)/(fabsf(tau)+sqrtf(1.f+tau*tau));
                float c = rsqrtf(1.f+t*t), s=t*c;
                float sg = up? -s : s;
                unsigned long long cp = pk2(c,c), sp = pk2(sg,sg);
                #pragma unroll
                for (int j=0;j<NP;j++) ap[j]=fma2(bp[j], sp, mul2(ap[j], cp));
                float cs2 = 2.f*c*s*z;
                x = up ? (c*c*xp + s*s*xq - cs2) : (s*s*xp + c*c*xq + cs2);
            }
        }
        if (!__any_sync(FULL,any)) break;
    }
}

template<int NP>
__device__ __forceinline__ float pnorm2(const unsigned long long (&ap)[NP]){
    unsigned long long acc = 0ull;
    #pragma unroll
    for (int j=0;j<NP;j++) acc = fma2(ap[j], ap[j], acc);
    float lo, hi; upk2(acc, lo, hi);
    return lo + hi;
}

// ---------------- per-thread 4x4 Jacobi eigh (registers) ----------------
__device__ void eigh4(float* a, float* v){
    #pragma unroll
    for (int i=0;i<16;i++) v[i] = ((i&3)==(i>>2)) ? 1.f : 0.f;
    #pragma unroll 1
    for (int sweep=0; sweep<10; sweep++){
        #pragma unroll
        for (int pr=0; pr<6; pr++){
            const int p = pr<3 ? 0 : (pr<5 ? 1 : 2);
            const int q = pr==0?1 : pr==1?2 : pr==2?3 : pr==3?2 : 3;
            float apq = a[p*4+q];
            float app=a[p*4+p], aqq=a[q*4+q];
            if (apq*apq > 1e-10f*fabsf(app*aqq) + 1e-38f){
                float tau=__fdividef(aqq-app,2.f*apq);
                float t=copysignf(1.f,tau)/(fabsf(tau)+sqrtf(1.f+tau*tau));
                float c=rsqrtf(1.f+t*t), s=t*c;
                #pragma unroll
                for (int j=0;j<4;j++){
                    float ajp=a[j*4+p], ajq=a[j*4+q];
                    a[j*4+p]=c*ajp-s*ajq; a[j*4+q]=s*ajp+c*ajq;
                }
                #pragma unroll
                for (int j=0;j<4;j++){
                    float apj=a[p*4+j], aqj=a[q*4+j];
                    a[p*4+j]=c*apj-s*aqj; a[q*4+j]=s*apj+c*aqj;
                }
                #pragma unroll
                for (int j=0;j<4;j++){
                    float vjp=v[j*4+p], vjq=v[j*4+q];
                    v[j*4+p]=c*vjp-s*vjq; v[j*4+q]=s*vjp+c*vjq;
                }
            }
        }
    }
}

// ---------------- kernel 0: fold BN into conv weights ----------------
__global__ void k_prep(const float* c1w,const float* c1b,const float* g1,const float* bb1,const float* m1,const float* v1,
                       const float* c2w,const float* c2b,const float* g2,const float* bb2,const float* m2,const float* v2){
    int tid=threadIdx.x;
    for (int i=tid;i<22*22;i+=256){int o=i/22; g_W1f[i]=c1w[i]*g1[o]*rsqrtf(v1[o]+1e-5f);}
    for (int o=tid;o<22;o+=256){float s=g1[o]*rsqrtf(v1[o]+1e-5f); g_b1f[o]=(c1b[o]-m1[o])*s+bb1[o];}
    for (int i=tid;i<25*22*12;i+=256){int p=i/(22*12); g_W2f[i]=c2w[i]*g2[p]*rsqrtf(v2[p]+1e-5f);}
    for (int p=tid;p<25;p+=256){float s=g2[p]*rsqrtf(v2[p]+1e-5f); g_b2f[p]=(c2b[p]-m2[p])*s+bb2[p];}
}

// ---------------- kernel 1: FUSED conv1+bn1+conv2+bn2 ----------------
// Output tile 256 wide; conv1 computed into smem over the 267-wide window.
__global__ __launch_bounds__(128) void k_conv12(const float* __restrict__ x){
    int b = blockIdx.y;
    int w0 = blockIdx.x*256;
    int tx = threadIdx.x;
    __shared__ float xs[22][268];
    __shared__ float ys[22][268];
    __shared__ __align__(16) float w2[25*22*12];
    __shared__ float w1[22*22];
    __shared__ float b1s[22], b2s[25];
    for (int i=tx;i<22*22;i+=128) w1[i]=g_W1f[i];
    for (int i=tx;i<25*22*12;i+=128) w2[i]=g_W2f[i];
    if (tx<22) b1s[tx]=g_b1f[tx];
    if (tx<25) b2s[tx]=g_b2f[tx];
    for (int h=0;h<22;h++){
        for (int j=tx;j<268;j+=128){
            int wi = w0 - 6 + j;
            xs[h][j] = (wi>=0 && wi<TLEN) ? x[(b*22+h)*TLEN + wi] : 0.f;
        }
    }
    __syncthreads();
    // conv1 + bn1 into ys (window positions 0..266; global v = w0-6+j)
    for (int j=tx; j<267; j+=128){
        float xv[22];
        #pragma unroll
        for (int h=0;h<22;h++) xv[h]=xs[h][j];
        int gv = w0 - 6 + j;
        bool valid = (gv>=0 && gv<TLEN);
        for (int o=0;o<22;o++){
            float acc=b1s[o];
            #pragma unroll
            for (int h=0;h<22;h++) acc += w1[o*22+h]*xv[h];
            ys[o][j]= valid ? acc : 0.f;
        }
    }
    __syncthreads();
    // conv2 + bn2, f32x2 two outputs per thread
    int w = w0 + 2*tx;
    if (w < T2){
        for (int p=0;p<25;p++){
            unsigned long long acc = pk2(b2s[p], b2s[p]);
            for (int o=0;o<22;o++){
                const float4* wr4 = reinterpret_cast<const float4*>(&w2[(p*22+o)*12]);
                float4 wa = wr4[0], wb = wr4[1], wc = wr4[2];
                float wv[12] = {wa.x,wa.y,wa.z,wa.w, wb.x,wb.y,wb.z,wb.w, wc.x,wc.y,wc.z,wc.w};
                const float* yo = &ys[o][2*tx];
                float yv[13];
                #pragma unroll
                for (int j=0;j<13;j++) yv[j]=yo[j];
                #pragma unroll
                for (int dw=0;dw<12;dw++)
                    acc = fma2(pk2(yv[dw], yv[dw+1]), pk2(wv[dw], wv[dw]), acc);
            }
            float lo,hi; upk2(acc,lo,hi);
            g_sig[(b*25+p)*T2 + w] = lo;
            if (w+1 < T2) g_sig[(b*25+p)*T2 + w + 1] = hi;
        }
    }
}

// ---------------- kernel 2: signal2spd, mean-centered f32x2 dot ----------
__global__ __launch_bounds__(256) void k_cov(){
    int t = blockIdx.x, b = blockIdx.y;
    int tid = threadIdx.x;
    int off = t*334;
    int L = (t<2)?334:333;
    const int LS = 334;
    __shared__ __align__(8) float sd[25*334];
    __shared__ float mu[25];
    __shared__ float raw[625];
    __shared__ float tr;
    for (int i=tid;i<25*LS;i+=256){
        int c=i/LS, tau=i%LS;
        sd[i] = (tau<L) ? g_sig[(b*25+c)*T2 + off + tau] : 0.f;
    }
    __syncthreads();
    if (tid<25){
        float s=0.f;
        for (int tau=0;tau<L;tau++) s += sd[tid*LS+tau];
        mu[tid]=s/(float)L;
    }
    __syncthreads();
    for (int i=tid;i<25*LS;i+=256){
        int c=i/LS, tau=i%LS;
        if (tau<L) sd[i] -= mu[c];
    }
    __syncthreads();
    for (int e=tid;e<625;e+=256){
        int c=e/25, d=e%25;
        const unsigned long long* rc=reinterpret_cast<const unsigned long long*>(&sd[c*LS]);
        const unsigned long long* rd=reinterpret_cast<const unsigned long long*>(&sd[d*LS]);
        unsigned long long acc=0ull;
        for (int j=0;j<LS/2;j++) acc = fma2(rc[j], rd[j], acc);
        float lo,hi; upk2(acc,lo,hi);
        raw[e]=lo+hi;
    }
    __syncthreads();
    if (tid==0){
        float s=0.f;
        for (int i=0;i<25;i++) s += raw[i*26];
        tr = s;
    }
    __syncthreads();
    float inv = 1.f/tr;
    for (int e=tid;e<625;e+=256){
        float v = raw[e]*inv;
        if (e/25 == e%25) v += 1e-5f;
        g_cov[(b*3+t)*625 + e] = v;
    }
}

// ---------------- kernel 3: attention weights per (epoch, batch) ----------
__global__ __launch_bounds__(64) void k_wts(
    const float* __restrict__ sq3,
    const float* __restrict__ sk0,const float* __restrict__ sk1,
    const float* __restrict__ sk2,const float* __restrict__ sk3)
{
    __shared__ float s_cov[625];
    __shared__ float s_sk[216];
    __shared__ float s_sq[100];
    __shared__ float s_K[480];
    __shared__ float s_Q[16];
    __shared__ float s_logQ[16];
    __shared__ float s_w[30];
    __shared__ float s_qn;

    int tid=threadIdx.x;
    int t=blockIdx.x, b=blockIdx.y;
    int bt=b*3+t;
    const float* covg = g_cov + bt*625;
    for (int i=tid;i<625;i+=64) s_cov[i]=covg[i];
    for (int i=tid;i<16;i+=64)  s_sk[i]=sk0[i];
    for (int i=tid;i<36;i+=64)  s_sk[16+i]=sk1[i];
    for (int i=tid;i<64;i+=64)  s_sk[52+i]=sk2[i];
    for (int i=tid;i<100;i+=64){ s_sk[116+i]=sk3[i]; s_sq[i]=sq3[i]; }
    __syncthreads();

    for (int e=tid;e<496;e+=64){
        if (e<480){
            int i=e>>4, ab=e&15;
            int aa=ab>>2, bb2=ab&3;
            int k,r0,c0,g; sub_info(i,k,r0,c0,g);
            int kk=k*k;
            const float* W = s_sk + ((g==0)?0:(g==1)?16:(g==2)?52:116);
            float acc=0.f;
            for (int ii=0;ii<kk;ii++){
                int gii=(r0+ii/k)*5+(c0+ii%k);
                const float* crow=&s_cov[gii*25];
                float partial=0.f;
                for (int jj=0;jj<kk;jj++){
                    int gjj=(r0+jj/k)*5+(c0+jj%k);
                    partial += crow[gjj]*W[jj*4+bb2];
                }
                acc += W[ii*4+aa]*partial;
            }
            if (aa==bb2) acc += 2.5e-5f*(float)(aa+1);
            s_K[i*16+ab]=acc;
        } else {
            int ab=e-480;
            int aa=ab>>2, bb2=ab&3;
            float acc=0.f;
            for (int ii=0;ii<25;ii++){
                const float* crow=&s_cov[ii*25];
                float partial=0.f;
                for (int jj=0;jj<25;jj++) partial += crow[jj]*s_sq[jj*4+bb2];
                acc += s_sq[ii*4+aa]*partial;
            }
            if (aa==bb2) acc += 2.5e-5f*(float)(aa+1);
            s_Q[ab]=acc;
        }
    }
    __syncthreads();

    float lmK[4]; float vK[16];
    bool haveK = (tid>=32 && tid<62);
    if (tid==0){
        float a[16], v[16];
        #pragma unroll
        for (int x=0;x<16;x++) a[x]=s_Q[x];
        eigh4(a,v);
        float lm[4];
        #pragma unroll
        for (int m=0;m<4;m++) lm[m]=logf(fmaxf(a[m*5],1e-9f));
        float qn=0.f;
        #pragma unroll
        for (int r=0;r<4;r++)
            #pragma unroll
            for (int c=0;c<4;c++){
                float ee=0.f;
                #pragma unroll
                for (int m=0;m<4;m++) ee += v[r*4+m]*lm[m]*v[c*4+m];
                s_logQ[r*4+c]=ee;
                qn += ee*ee;
            }
        s_qn=qn;
    }
    if (haveK){
        int i=tid-32;
        float a[16];
        #pragma unroll
        for (int x=0;x<16;x++) a[x]=s_K[i*16+x];
        eigh4(a,vK);
        #pragma unroll
        for (int m=0;m<4;m++) lmK[m]=logf(fmaxf(a[m*5],1e-9f));
    }
    __syncthreads();
    if (haveK){
        int i=tid-32;
        float kn=0.f, cr=0.f;
        #pragma unroll
        for (int r=0;r<4;r++)
            #pragma unroll
            for (int c=0;c<4;c++){
                float ee=0.f;
                #pragma unroll
                for (int m=0;m<4;m++) ee += vK[r*4+m]*lmK[m]*vK[c*4+m];
                kn += ee*ee;
                cr += ee*s_logQ[r*4+c];
            }
        float E=fmaxf(kn + s_qn - 2.f*cr, 0.f);
        s_w[i]=1.f/(1.f+log1pf(E));
    }
    __syncthreads();
    if (tid==0){
        float mx=-1e30f;
        for (int i=0;i<30;i++) mx=fmaxf(mx,s_w[i]);
        float sm=0.f;
        for (int i=0;i<30;i++){float e=expf(s_w[i]-mx); s_w[i]=e; sm+=e;}
        float inv=1.f/sm;
        for (int i=0;i<30;i++) g_w[bt*30+i]=s_w[i]*inv;
    }
}

// ---------------- kernel 4: one-sided Jacobi 25x25 V-eigh per warp ----------
__global__ __launch_bounds__(128) void k_veigh(
    const float* __restrict__ sv0,const float* __restrict__ sv1,
    const float* __restrict__ sv2,const float* __restrict__ sv3)
{
    __shared__ float s_cov[625];
    __shared__ float s_sv[1350];
    __shared__ float s_C[4][675];   // lda 27
    __shared__ float s_G[4][675];
    __shared__ int   s_gi[4][25];

    int tid=threadIdx.x, lane=tid&31, wid=tid>>5;
    int bt = blockIdx.z*3 + blockIdx.y;
    const float* covg = g_cov + bt*625;
    for (int i=tid;i<625;i+=128) s_cov[i]=covg[i];
    for (int i=tid;i<100;i+=128) s_sv[i]=sv0[i];
    for (int i=tid;i<225;i+=128) s_sv[100+i]=sv1[i];
    for (int i=tid;i<400;i+=128) s_sv[325+i]=sv2[i];
    for (int i=tid;i<625;i+=128) s_sv[725+i]=sv3[i];
    __syncthreads();

    int i = blockIdx.x*4 + wid;
    if (i >= 30) return;
    int k,r0,c0,g; sub_info(i,k,r0,c0,g);
    int kk=k*k;
    const float* Wv = s_sv + ((g==0)?0:(g==1)?100:(g==2)?325:725);
    if (lane<kk) s_gi[wid][lane]=(r0+lane/k)*5+(c0+lane%k);
    __syncwarp();
    for (int e=lane;e<kk*25;e+=32){
        int r=e/25, c=e%25;
        const float* crow=&s_cov[s_gi[wid][r]*25];
        float s=0.f;
        for (int jj=0;jj<kk;jj++) s += crow[s_gi[wid][jj]]*Wv[jj*25+c];
        s_G[wid][e]=s;
    }
    __syncwarp();
    for (int e=lane;e<625;e+=32){
        int a=e/25, bb=e%25;
        float s=0.f;
        for (int r=0;r<kk;r++) s += Wv[r*25+a]*s_G[wid][r*25+bb];
        if (a==bb) s += 4e-6f*(float)(a+1);
        s_C[wid][a*27+bb]=s;
    }
    __syncwarp();

    unsigned long long ap[13];
    float x = 0.f;
    if (lane < 25){
        #pragma unroll
        for (int j=0;j<12;j++) ap[j]=pk2(s_C[wid][(2*j)*27+lane], s_C[wid][(2*j+1)*27+lane]);
        ap[12]=pk2(s_C[wid][24*27+lane], 0.f);
        x = pnorm2<13>(ap);
    } else {
        #pragma unroll
        for (int j=0;j<13;j++) ap[j]=0ull;
    }

    hestenes_p<25>(ap, x, lane, 12);

    float xf = pnorm2<13>(ap);
    float wt = g_w[bt*30+i];
    float xs2 = fmaxf(xf, 1e-18f);
    float gsc = 0.5f*wt*__logf(xs2) / fmaxf(xf, 1e-30f);

    if (lane<25){
        #pragma unroll
        for (int j=0;j<12;j++){
            float lo,hi; upk2(ap[j],lo,hi);
            s_C[wid][(2*j)*27+lane]=lo;   s_C[wid][(2*j+1)*27+lane]=hi;
            s_G[wid][(2*j)*27+lane]=gsc*lo; s_G[wid][(2*j+1)*27+lane]=gsc*hi;
        }
        float lo,hi; upk2(ap[12],lo,hi);
        s_C[wid][24*27+lane]=lo;
        s_G[wid][24*27+lane]=gsc*lo;
    }
    __syncwarp();
    float* outp = g_logV + (bt*30+i)*625;
    for (int e=lane;e<325;e+=32){
        int r,c; tri25(e,r,c);
        float s=0.f;
        for (int m=0;m<25;m++) s += s_G[wid][r*27+m]*s_C[wid][c*27+m];
        outp[r*25+c]=s;
        if (r!=c) outp[c*25+r]=s;
    }
}

// ---------------- kernel 5: sum + eigh + Rayleigh + exp/rect, 1 warp per bt
__global__ __launch_bounds__(128) void k_s1fin(){
    __shared__ float s_L[4][675];   // lda 27, kept intact for Rayleigh
    __shared__ float s_C[4][675];
    __shared__ float s_G[4][675];

    int tid=threadIdx.x, lane=tid&31, wid=tid>>5;
    int bt=blockIdx.x*4+wid;        // grid 192 covers 768
    float* L = s_L[wid];
    const float* base = g_logV + bt*30*625;
    for (int e=lane;e<625;e+=32){
        float s=0.f;
        for (int i=0;i<30;i++) s += base[i*625+e];
        L[(e/25)*27+(e%25)]=s;
    }
    __syncwarp();

    unsigned long long ap[13];
    float x=0.f;
    if (lane<25){
        #pragma unroll
        for (int j=0;j<12;j++) ap[j]=pk2(L[(2*j)*27+lane], L[(2*j+1)*27+lane]);
        ap[12]=pk2(L[24*27+lane], 0.f);
        x = pnorm2<13>(ap);
    } else {
        #pragma unroll
        for (int j=0;j<13;j++) ap[j]=0ull;
    }

    hestenes_p<25>(ap, x, lane, 12);

    float av[25];
    if (lane<25){
        #pragma unroll
        for (int j=0;j<12;j++) upk2(ap[j], av[2*j], av[2*j+1]);
        float hi_d; upk2(ap[12], av[24], hi_d);
    } else {
        #pragma unroll
        for (int j=0;j<25;j++) av[j]=0.f;
    }
    float xf = pnorm2<13>(ap);
    float num=0.f;
    if (lane<25){
        #pragma unroll 1
        for (int j=0;j<25;j++){
            float t=0.f;
            #pragma unroll
            for (int kx=0;kx<25;kx++) t += L[j*27+kx]*av[kx];
            num += av[j]*t;
        }
    }
    float lam = num / fmaxf(xf, 1e-30f);
    float mu = fmaxf(__expf(lam), 1e-4f);
    float coef = mu / fmaxf(xf, 1e-30f);
    if (lane<25){
        #pragma unroll
        for (int j=0;j<25;j++){
            s_C[wid][j*27+lane]=av[j];
            s_G[wid][j*27+lane]=coef*av[j];
        }
    }
    __syncwarp();
    float* xo = g_xm + bt*625;
    for (int e=lane;e<325;e+=32){
        int r,c; tri25(e,r,c);
        float s=0.f;
        for (int m=0;m<25;m++) s += s_G[wid][r*27+m]*s_C[wid][c*27+m];
        xo[r*25+c]=s;
        if (r!=c) xo[c*25+r]=s;
    }
}

// ---------------- kernel 6: stage-2 attention + feat + linear ----------------
__global__ __launch_bounds__(128) void k_stage2(
    const float* __restrict__ mq,const float* __restrict__ mk,const float* __restrict__ mv,
    const float* __restrict__ lw,const float* __restrict__ lb,float* __restrict__ out)
{
    __shared__ float s_xm[1875];
    __shared__ float s_W[3][450];
    __shared__ float s_M[9][324];
    __shared__ float s_A[4][342];   // 18x18, lda 19
    __shared__ float s_U[4][342];
    __shared__ float s_tmp[4][450];
    __shared__ float s_norm[9];
    __shared__ float s_P[3][3];
    __shared__ float s_feat[513];

    int tid=threadIdx.x, lane=tid&31, wid=tid>>5;
    int b=blockIdx.x;
    for (int i=tid;i<1875;i+=128) s_xm[i]=g_xm[b*1875+i];
    for (int i=tid;i<450;i+=128){ s_W[0][i]=mq[i]; s_W[1][i]=mk[i]; s_W[2][i]=mv[i]; }
    __syncthreads();

    for (int task=wid; task<9; task+=4){
        int t=task/3, which=task%3;
        const float* X=&s_xm[t*625];
        const float* W=s_W[which];
        float* tmp=s_tmp[wid];
        for (int e=lane;e<450;e+=32){
            int r=e/18,c=e%18;
            float s=0.f;
            for (int j=0;j<25;j++) s += X[r*25+j]*W[j*18+c];
            tmp[e]=s;
        }
        __syncwarp();
        for (int e=lane;e<324;e+=32){
            int a=e/18,bb=e%18;
            float s=0.f;
            for (int r=0;r<25;r++) s += W[r*18+a]*tmp[r*18+bb];
            s_A[wid][a*19+bb]=s;
        }
        __syncwarp();
        unsigned long long ap[9];
        float x=0.f;
        if (lane<18){
            #pragma unroll
            for (int j=0;j<9;j++) ap[j]=pk2(s_A[wid][(2*j)*19+lane], s_A[wid][(2*j+1)*19+lane]);
            x = pnorm2<9>(ap);
        } else {
            #pragma unroll
            for (int j=0;j<9;j++) ap[j]=0ull;
        }

        hestenes_p<18>(ap, x, lane, 10);

        float xf = pnorm2<9>(ap);
        float lgl = 0.5f*__logf(fmaxf(xf,1e-18f));
        float gcf = lgl / fmaxf(xf,1e-30f);
        if (lane<18){
            #pragma unroll
            for (int j=0;j<9;j++){
                float lo,hi; upk2(ap[j],lo,hi);
                s_A[wid][(2*j)*19+lane]=lo;     s_A[wid][(2*j+1)*19+lane]=hi;
                s_U[wid][(2*j)*19+lane]=gcf*lo; s_U[wid][(2*j+1)*19+lane]=gcf*hi;
            }
        }
        __syncwarp();
        float nrm=0.f;
        for (int e=lane;e<171;e+=32){
            int r,c; tri18(e,r,c);
            float s=0.f;
            for (int m=0;m<18;m++) s += s_U[wid][r*19+m]*s_A[wid][c*19+m];
            s_M[task][r*18+c]=s;
            s_M[task][c*18+r]=s;
            nrm += (r==c) ? s*s : 2.f*s*s;
        }
        nrm=warp_sum(nrm);
        if (lane==0) s_norm[task]=nrm;
        __syncwarp();
    }
    __syncthreads();

    for (int pr=wid; pr<9; pr+=4){
        int i=pr/3, j=pr%3;
        const float* LK=s_M[i*3+1];
        const float* LQ=s_M[j*3+0];
        float cr=0.f;
        for (int e=lane;e<324;e+=32) cr += LK[e]*LQ[e];
        cr=warp_sum(cr);
        if (lane==0){
            float E=fmaxf(s_norm[i*3+1]+s_norm[j*3+0]-2.f*cr,0.f);
            s_P[i][j]=1.f/(1.f+log1pf(E));
        }
    }
    __syncthreads();
    if (tid==0){
        for (int j=0;j<3;j++){
            float m=fmaxf(fmaxf(s_P[0][j],s_P[1][j]),s_P[2][j]);
            float e0=expf(s_P[0][j]-m), e1=expf(s_P[1][j]-m), e2=expf(s_P[2][j]-m);
            float inv=1.f/(e0+e1+e2);
            s_P[0][j]=e0*inv; s_P[1][j]=e1*inv; s_P[2][j]=e2*inv;
        }
    }
    __syncthreads();

    // last 3: out_log >= ln(1e-4)*I -> A+10I PSD, shifted one-sided Jacobi
    if (wid<3){
        int j=wid;
        float p0=s_P[0][j], p1=s_P[1][j], p2=s_P[2][j];
        for (int e=lane;e<324;e+=32){
            int r=e/18,c=e%18;
            float v = p0*s_M[2][e]+p1*s_M[5][e]+p2*s_M[8][e];
            if (r==c) v += 10.f;
            s_A[wid][r*19+c]=v;
        }
        __syncwarp();
        unsigned long long ap[9];
        float x=0.f;
        if (lane<18){
            #pragma unroll
            for (int jj=0;jj<9;jj++) ap[jj]=pk2(s_A[wid][(2*jj)*19+lane], s_A[wid][(2*jj+1)*19+lane]);
            x = pnorm2<9>(ap);
        } else {
            #pragma unroll
            for (int jj=0;jj<9;jj++) ap[jj]=0ull;
        }

        hestenes_p<18>(ap, x, lane, 10);

        float xf = pnorm2<9>(ap);
        float lamp = sqrtf(fmaxf(xf,1e-30f));
        float lam  = fmaxf(lamp - 10.f, -9.2103403719761818f);
        float gcf  = lam / fmaxf(xf,1e-30f);
        if (lane<18){
            #pragma unroll
            for (int jj=0;jj<9;jj++){
                float lo,hi; upk2(ap[jj],lo,hi);
                s_A[wid][(2*jj)*19+lane]=lo;     s_A[wid][(2*jj+1)*19+lane]=hi;
                s_U[wid][(2*jj)*19+lane]=gcf*lo; s_U[wid][(2*jj+1)*19+lane]=gcf*hi;
            }
        }
        __syncwarp();
        for (int e=lane;e<171;e+=32){
            int r,c; tri18(e,r,c);
            float s=0.f;
            for (int m=0;m<18;m++) s += s_U[wid][r*19+m]*s_A[wid][c*19+m];
            float coef=(r==c)?1.f:1.41421356237309515f;
            int p = r*18 - (r*(r-1))/2 + (c-r);
            s_feat[j*171+p]=coef*s;
        }
    }
    __syncthreads();

    {
        int o=wid;
        float s=0.f;
        for (int f=lane;f<513;f+=32) s += s_feat[f]*lw[o*513+f];
        s=warp_sum(s);
        if (lane==0) out[b*4+o]=s+lb[o];
    }
}

extern "C" void kernel_launch(void* const* d_in, const int* in_sizes, int n_in,
                              void* d_out, int out_size) {
    const float* x    = (const float*)d_in[0];
    const float* c1w  = (const float*)d_in[1];
    const float* c1b  = (const float*)d_in[2];
    const float* bn1g = (const float*)d_in[3];
    const float* bn1b = (const float*)d_in[4];
    const float* bn1m = (const float*)d_in[5];
    const float* bn1v = (const float*)d_in[6];
    const float* c2w  = (const float*)d_in[7];
    const float* c2b  = (const float*)d_in[8];
    const float* bn2g = (const float*)d_in[9];
    const float* bn2b = (const float*)d_in[10];
    const float* bn2m = (const float*)d_in[11];
    const float* bn2v = (const float*)d_in[12];

    const float *sq[4], *sk[4], *sv[4];
    if (in_sizes[13]==16 && in_sizes[14]==16 && in_sizes[15]==100){
        for (int i=0;i<4;i++){
            sq[i] = (const float*)d_in[13+3*i];
            sk[i] = (const float*)d_in[14+3*i];
            sv[i] = (const float*)d_in[15+3*i];
        }
    } else {
        for (int i=0;i<4;i++){
            sq[i] = (const float*)d_in[13+i];
            sk[i] = (const float*)d_in[17+i];
            sv[i] = (const float*)d_in[21+i];
        }
    }
    const float* mq   = (const float*)d_in[25];
    const float* mk   = (const float*)d_in[26];
    const float* mv   = (const float*)d_in[27];
    const float* lw   = (const float*)d_in[28];
    const float* lb   = (const float*)d_in[29];
    float* out = (float*)d_out;

    k_prep<<<1,256>>>(c1w,c1b,bn1g,bn1b,bn1m,bn1v,c2w,c2b,bn2g,bn2b,bn2m,bn2v);
    k_conv12<<<dim3(4,NB),128>>>(x);
    k_cov<<<dim3(3,NB),256>>>();
    k_wts<<<dim3(3,NB),64>>>(sq[3],sk[0],sk[1],sk[2],sk[3]);
    k_veigh<<<dim3(8,3,NB),128>>>(sv[0],sv[1],sv[2],sv[3]);
    k_s1fin<<<192,128>>>();
    k_stage2<<<NB,128>>>(mq,mk,mv,lw,lb,out);
}

// round 16
// speedup vs baseline: 1.0436x; 1.0436x over previous
#include <cuda_runtime.h>
#include <cuda_bf16.h>

#define NB 256
#define TLEN 1000
#define T2 1001

// ---------------- device scratch (static, allocation-free) ----------------
__device__ float g_W1f[22*22];
__device__ float g_b1f[22];
__device__ float g_W2f[25*22*12];
__device__ float g_b2f[25];
__device__ float g_y1[NB*22*TLEN];
__device__ float g_sig[NB*25*T2];
__device__ float g_cov[NB*3*625];
__device__ float g_w[NB*3*30];
__device__ float g_logV[NB*3*30*625];   // weighted log(V_i), 57.6MB
__device__ float g_xm[NB*3*625];

// ---------------- helpers ----------------
__device__ __forceinline__ float warp_sum(float v){
    #pragma unroll
    for (int o=16;o;o>>=1) v += __shfl_xor_sync(0xffffffffu, v, o);
    return v;
}

__device__ __forceinline__ void sub_info(int i,int&k,int&r0,int&c0,int&g){
    if(i<16){g=0;k=2;r0=i>>2;c0=i&3;}
    else if(i<25){g=1;k=3;int s=i-16;r0=s/3;c0=s%3;}
    else if(i<29){g=2;k=4;int s=i-25;r0=s>>1;c0=s&1;}
    else{g=3;k=5;r0=0;c0=0;}
}

// triangular-index -> (r,c), r<=c
__device__ __forceinline__ void tri25(int e,int&r,int&c){
    int rr = (int)((51.f - sqrtf(2601.f - 8.f*(float)e)) * 0.5f);
    if (rr > 0 && (rr*(51-rr))/2 > e) rr--;
    while (((rr+1)*(50-rr))/2 <= e) rr++;
    r = rr;
    c = rr + (e - (rr*(51-rr))/2);
}
__device__ __forceinline__ void tri18(int e,int&r,int&c){
    int rr = (int)((37.f - sqrtf(1369.f - 8.f*(float)e)) * 0.5f);
    if (rr > 0 && (rr*(37-rr))/2 > e) rr--;
    while (((rr+1)*(36-rr))/2 <= e) rr++;
    r = rr;
    c = rr + (e - (rr*(37-rr))/2);
}

// ---------------- f32x2 packed helpers (sm_103a dual-FP32 path) ------------
__device__ __forceinline__ unsigned long long pk2(float lo, float hi){
    unsigned long long r;
    asm("mov.b64 %0,{%1,%2};" : "=l"(r) : "f"(lo), "f"(hi));
    return r;
}
__device__ __forceinline__ void upk2(unsigned long long v, float& lo, float& hi){
    asm("mov.b64 {%0,%1},%2;" : "=f"(lo), "=f"(hi) : "l"(v));
}
__device__ __forceinline__ unsigned long long fma2(unsigned long long a, unsigned long long b, unsigned long long c){
    unsigned long long d;
    asm("fma.rn.f32x2 %0, %1, %2, %3;" : "=l"(d) : "l"(a), "l"(b), "l"(c));
    return d;
}
__device__ __forceinline__ unsigned long long mul2(unsigned long long a, unsigned long long b){
    unsigned long long d;
    asm("mul.rn.f32x2 %0, %1, %2;" : "=l"(d) : "l"(a), "l"(b));
    return d;
}

// ---------------- one-sided (Hestenes) Jacobi, f32x2-packed columns --------
template<int N>
__device__ __forceinline__ void hestenes_p(unsigned long long (&ap)[(N+1)/2], float &x, int lane, int max_sweeps){
    constexpr int NP = (N + 1) / 2;
    constexpr int ROT = (N & 1) ? N : (N - 1);
    const unsigned FULL = 0xffffffffu;
    for (int sweep=0; sweep<max_sweeps; sweep++){
        int any=0;
        for (int r=0;r<ROT;r++){
            int partner;
            if (lane > ROT) partner = lane;
            else if (lane == ROT) partner = (ROT - r) % ROT;
            else {
                int pos = lane + r; if (pos >= ROT) pos -= ROT;
                if (pos == 0) partner = ROT;
                else { int pl = ROT - pos - r; if (pl < 0) pl += ROT; partner = pl; }
            }
            unsigned long long bp[NP];
            #pragma unroll
            for (int j=0;j<NP;j++) bp[j]=__shfl_sync(FULL,ap[j],partner);
            float y=__shfl_sync(FULL,x,partner);
            unsigned long long zacc = 0ull;
            #pragma unroll
            for (int j=0;j<NP;j++) zacc = fma2(ap[j], bp[j], zacc);
            float zlo, zhi; upk2(zacc, zlo, zhi);
            float z = zlo + zhi;
            if (lane<N && partner<N && z*z > 3e-8f*x*y + 1e-37f){
                any=1;
                bool up = lane<partner;
                float xp = up?x:y, xq = up?y:x;
                float tau = __fdividef(xq-xp, 2.f*z);
                float t = copysignf(1.f,tau)/(fabsf(tau)+sqrtf(1.f+tau*tau));
                float c = rsqrtf(1.f+t*t), s=t*c;
                float sg = up? -s : s;
                unsigned long long cp = pk2(c,c), sp = pk2(sg,sg);
                #pragma unroll
                for (int j=0;j<NP;j++) ap[j]=fma2(bp[j], sp, mul2(ap[j], cp));
                float cs2 = 2.f*c*s*z;
                x = up ? (c*c*xp + s*s*xq - cs2) : (s*s*xp + c*c*xq + cs2);
            }
        }
        if (!__any_sync(FULL,any)) break;
    }
}

template<int NP>
__device__ __forceinline__ float pnorm2(const unsigned long long (&ap)[NP]){
    unsigned long long acc = 0ull;
    #pragma unroll
    for (int j=0;j<NP;j++) acc = fma2(ap[j], ap[j], acc);
    float lo, hi; upk2(acc, lo, hi);
    return lo + hi;
}

// ---------------- per-thread 4x4 Jacobi eigh (registers) ----------------
__device__ void eigh4(float* a, float* v){
    #pragma unroll
    for (int i=0;i<16;i++) v[i] = ((i&3)==(i>>2)) ? 1.f : 0.f;
    #pragma unroll 1
    for (int sweep=0; sweep<10; sweep++){
        #pragma unroll
        for (int pr=0; pr<6; pr++){
            const int p = pr<3 ? 0 : (pr<5 ? 1 : 2);
            const int q = pr==0?1 : pr==1?2 : pr==2?3 : pr==3?2 : 3;
            float apq = a[p*4+q];
            float app=a[p*4+p], aqq=a[q*4+q];
            if (apq*apq > 1e-10f*fabsf(app*aqq) + 1e-38f){
                float tau=__fdividef(aqq-app,2.f*apq);
                float t=copysignf(1.f,tau)/(fabsf(tau)+sqrtf(1.f+tau*tau));
                float c=rsqrtf(1.f+t*t), s=t*c;
                #pragma unroll
                for (int j=0;j<4;j++){
                    float ajp=a[j*4+p], ajq=a[j*4+q];
                    a[j*4+p]=c*ajp-s*ajq; a[j*4+q]=s*ajp+c*ajq;
                }
                #pragma unroll
                for (int j=0;j<4;j++){
                    float apj=a[p*4+j], aqj=a[q*4+j];
                    a[p*4+j]=c*apj-s*aqj; a[q*4+j]=s*apj+c*aqj;
                }
                #pragma unroll
                for (int j=0;j<4;j++){
                    float vjp=v[j*4+p], vjq=v[j*4+q];
                    v[j*4+p]=c*vjp-s*vjq; v[j*4+q]=s*vjp+c*vjq;
                }
            }
        }
    }
}

// ---------------- kernel 0: fold BN into conv weights ----------------
__global__ void k_prep(const float* c1w,const float* c1b,const float* g1,const float* bb1,const float* m1,const float* v1,
                       const float* c2w,const float* c2b,const float* g2,const float* bb2,const float* m2,const float* v2){
    int tid=threadIdx.x;
    for (int i=tid;i<22*22;i+=256){int o=i/22; g_W1f[i]=c1w[i]*g1[o]*rsqrtf(v1[o]+1e-5f);}
    for (int o=tid;o<22;o+=256){float s=g1[o]*rsqrtf(v1[o]+1e-5f); g_b1f[o]=(c1b[o]-m1[o])*s+bb1[o];}
    for (int i=tid;i<25*22*12;i+=256){int p=i/(22*12); g_W2f[i]=c2w[i]*g2[p]*rsqrtf(v2[p]+1e-5f);}
    for (int p=tid;p<25;p+=256){float s=g2[p]*rsqrtf(v2[p]+1e-5f); g_b2f[p]=(c2b[p]-m2[p])*s+bb2[p];}
}

// ---------------- kernel 1: conv1 (22x22 channel mix) + bn1 ----------------
__global__ __launch_bounds__(128) void k_conv1(const float* __restrict__ x){
    int b = blockIdx.y;
    int tx = threadIdx.x;
    int w = blockIdx.x*128 + tx;
    __shared__ float xs[22][128];
    __shared__ float wf[22*22];
    __shared__ float bf[22];
    for (int i=tx;i<22*22;i+=128) wf[i]=g_W1f[i];
    if (tx<22) bf[tx]=g_b1f[tx];
    for (int h=0;h<22;h++) xs[h][tx] = (w<TLEN) ? x[(b*22+h)*TLEN + w] : 0.f;
    __syncthreads();
    if (w < TLEN){
        for (int o=0;o<22;o++){
            float acc = bf[o];
            #pragma unroll
            for (int h=0;h<22;h++) acc += wf[o*22+h]*xs[h][tx];
            g_y1[(b*22+o)*TLEN + w] = acc;
        }
    }
}

// ---------------- kernel 2: conv2 (22->25, kw=12, pad 6), f32x2 2 out/thread
__global__ __launch_bounds__(128) void k_conv2(){
    int b = blockIdx.y;
    int w0 = blockIdx.x*256;
    int tx = threadIdx.x;
    __shared__ float ys[22][268];
    __shared__ __align__(16) float w2[25*22*12];
    __shared__ float b2[25];
    for (int i=tx;i<25*22*12;i+=128) w2[i]=g_W2f[i];
    if (tx<25) b2[tx]=g_b2f[tx];
    for (int h=0;h<22;h++){
        for (int j=tx;j<268;j+=128){
            int wi = w0 - 6 + j;
            ys[h][j] = (wi>=0 && wi<TLEN) ? g_y1[(b*22+h)*TLEN + wi] : 0.f;
        }
    }
    __syncthreads();
    int w = w0 + 2*tx;
    if (w < T2){
        for (int p=0;p<25;p++){
            unsigned long long acc = pk2(b2[p], b2[p]);
            for (int o=0;o<22;o++){
                const float4* wr4 = reinterpret_cast<const float4*>(&w2[(p*22+o)*12]);
                float4 wa = wr4[0], wb = wr4[1], wc = wr4[2];
                float wv[12] = {wa.x,wa.y,wa.z,wa.w, wb.x,wb.y,wb.z,wb.w, wc.x,wc.y,wc.z,wc.w};
                const float* yo = &ys[o][2*tx];
                float yv[13];
                #pragma unroll
                for (int j=0;j<13;j++) yv[j]=yo[j];
                #pragma unroll
                for (int dw=0;dw<12;dw++)
                    acc = fma2(pk2(yv[dw], yv[dw+1]), pk2(wv[dw], wv[dw]), acc);
            }
            float lo,hi; upk2(acc,lo,hi);
            g_sig[(b*25+p)*T2 + w] = lo;
            if (w+1 < T2) g_sig[(b*25+p)*T2 + w + 1] = hi;
        }
    }
}

// ---------------- kernel 3: signal2spd, mean-centered f32x2 dot ----------
__global__ __launch_bounds__(256) void k_cov(){
    int t = blockIdx.x, b = blockIdx.y;
    int tid = threadIdx.x;
    int off = t*334;
    int L = (t<2)?334:333;
    const int LS = 334;
    __shared__ __align__(8) float sd[25*334];
    __shared__ float mu[25];
    __shared__ float raw[625];
    __shared__ float tr;
    for (int i=tid;i<25*LS;i+=256){
        int c=i/LS, tau=i%LS;
        sd[i] = (tau<L) ? g_sig[(b*25+c)*T2 + off + tau] : 0.f;
    }
    __syncthreads();
    if (tid<25){
        float s=0.f;
        for (int tau=0;tau<L;tau++) s += sd[tid*LS+tau];
        mu[tid]=s/(float)L;
    }
    __syncthreads();
    for (int i=tid;i<25*LS;i+=256){
        int c=i/LS, tau=i%LS;
        if (tau<L) sd[i] -= mu[c];
    }
    __syncthreads();
    for (int e=tid;e<625;e+=256){
        int c=e/25, d=e%25;
        const unsigned long long* rc=reinterpret_cast<const unsigned long long*>(&sd[c*LS]);
        const unsigned long long* rd=reinterpret_cast<const unsigned long long*>(&sd[d*LS]);
        unsigned long long acc=0ull;
        for (int j=0;j<LS/2;j++) acc = fma2(rc[j], rd[j], acc);
        float lo,hi; upk2(acc,lo,hi);
        raw[e]=lo+hi;
    }
    __syncthreads();
    if (tid==0){
        float s=0.f;
        for (int i=0;i<25;i++) s += raw[i*26];
        tr = s;
    }
    __syncthreads();
    float inv = 1.f/tr;
    for (int e=tid;e<625;e+=256){
        float v = raw[e]*inv;
        if (e/25 == e%25) v += 1e-5f;
        g_cov[(b*3+t)*625 + e] = v;
    }
}

// ---------------- kernel 4a: attention weights per (epoch, batch) ----------
// block 256 (was 64): the 496-element build loop dominates; occupancy fix.
__global__ __launch_bounds__(256) void k_wts(
    const float* __restrict__ sq3,
    const float* __restrict__ sk0,const float* __restrict__ sk1,
    const float* __restrict__ sk2,const float* __restrict__ sk3)
{
    __shared__ float s_cov[625];
    __shared__ float s_sk[216];
    __shared__ float s_sq[100];
    __shared__ float s_K[480];
    __shared__ float s_Q[16];
    __shared__ float s_logQ[16];
    __shared__ float s_w[30];
    __shared__ float s_qn;

    int tid=threadIdx.x;
    int t=blockIdx.x, b=blockIdx.y;
    int bt=b*3+t;
    const float* covg = g_cov + bt*625;
    for (int i=tid;i<625;i+=256) s_cov[i]=covg[i];
    for (int i=tid;i<16;i+=256)  s_sk[i]=sk0[i];
    for (int i=tid;i<36;i+=256)  s_sk[16+i]=sk1[i];
    for (int i=tid;i<64;i+=256)  s_sk[52+i]=sk2[i];
    for (int i=tid;i<100;i+=256){ s_sk[116+i]=sk3[i]; s_sq[i]=sq3[i]; }
    __syncthreads();

    for (int e=tid;e<496;e+=256){
        if (e<480){
            int i=e>>4, ab=e&15;
            int aa=ab>>2, bb2=ab&3;
            int k,r0,c0,g; sub_info(i,k,r0,c0,g);
            int kk=k*k;
            const float* W = s_sk + ((g==0)?0:(g==1)?16:(g==2)?52:116);
            float acc=0.f;
            for (int ii=0;ii<kk;ii++){
                int gii=(r0+ii/k)*5+(c0+ii%k);
                const float* crow=&s_cov[gii*25];
                float partial=0.f;
                for (int jj=0;jj<kk;jj++){
                    int gjj=(r0+jj/k)*5+(c0+jj%k);
                    partial += crow[gjj]*W[jj*4+bb2];
                }
                acc += W[ii*4+aa]*partial;
            }
            if (aa==bb2) acc += 2.5e-5f*(float)(aa+1);
            s_K[i*16+ab]=acc;
        } else {
            int ab=e-480;
            int aa=ab>>2, bb2=ab&3;
            float acc=0.f;
            for (int ii=0;ii<25;ii++){
                const float* crow=&s_cov[ii*25];
                float partial=0.f;
                for (int jj=0;jj<25;jj++) partial += crow[jj]*s_sq[jj*4+bb2];
                acc += s_sq[ii*4+aa]*partial;
            }
            if (aa==bb2) acc += 2.5e-5f*(float)(aa+1);
            s_Q[ab]=acc;
        }
    }
    __syncthreads();

    float lmK[4]; float vK[16];
    bool haveK = (tid>=32 && tid<62);
    if (tid==0){
        float a[16], v[16];
        #pragma unroll
        for (int x=0;x<16;x++) a[x]=s_Q[x];
        eigh4(a,v);
        float lm[4];
        #pragma unroll
        for (int m=0;m<4;m++) lm[m]=logf(fmaxf(a[m*5],1e-9f));
        float qn=0.f;
        #pragma unroll
        for (int r=0;r<4;r++)
            #pragma unroll
            for (int c=0;c<4;c++){
                float ee=0.f;
                #pragma unroll
                for (int m=0;m<4;m++) ee += v[r*4+m]*lm[m]*v[c*4+m];
                s_logQ[r*4+c]=ee;
                qn += ee*ee;
            }
        s_qn=qn;
    }
    if (haveK){
        int i=tid-32;
        float a[16];
        #pragma unroll
        for (int x=0;x<16;x++) a[x]=s_K[i*16+x];
        eigh4(a,vK);
        #pragma unroll
        for (int m=0;m<4;m++) lmK[m]=logf(fmaxf(a[m*5],1e-9f));
    }
    __syncthreads();
    if (haveK){
        int i=tid-32;
        float kn=0.f, cr=0.f;
        #pragma unroll
        for (int r=0;r<4;r++)
            #pragma unroll
            for (int c=0;c<4;c++){
                float ee=0.f;
                #pragma unroll
                for (int m=0;m<4;m++) ee += vK[r*4+m]*lmK[m]*vK[c*4+m];
                kn += ee*ee;
                cr += ee*s_logQ[r*4+c];
            }
        float E=fmaxf(kn + s_qn - 2.f*cr, 0.f);
        s_w[i]=1.f/(1.f+log1pf(E));
    }
    __syncthreads();
    if (tid==0){
        float mx=-1e30f;
        for (int i=0;i<30;i++) mx=fmaxf(mx,s_w[i]);
        float sm=0.f;
        for (int i=0;i<30;i++){float e=expf(s_w[i]-mx); s_w[i]=e; sm+=e;}
        float inv=1.f/sm;
        for (int i=0;i<30;i++) g_w[bt*30+i]=s_w[i]*inv;
    }
}

// ---------------- kernel 4b: one-sided Jacobi 25x25 V-eigh per warp ----------
__global__ __launch_bounds__(128) void k_veigh(
    const float* __restrict__ sv0,const float* __restrict__ sv1,
    const float* __restrict__ sv2,const float* __restrict__ sv3)
{
    __shared__ float s_cov[625];
    __shared__ float s_sv[1350];
    __shared__ float s_C[4][675];   // lda 27
    __shared__ float s_G[4][675];
    __shared__ int   s_gi[4][25];

    int tid=threadIdx.x, lane=tid&31, wid=tid>>5;
    int bt = blockIdx.z*3 + blockIdx.y;
    const float* covg = g_cov + bt*625;
    for (int i=tid;i<625;i+=128) s_cov[i]=covg[i];
    for (int i=tid;i<100;i+=128) s_sv[i]=sv0[i];
    for (int i=tid;i<225;i+=128) s_sv[100+i]=sv1[i];
    for (int i=tid;i<400;i+=128) s_sv[325+i]=sv2[i];
    for (int i=tid;i<625;i+=128) s_sv[725+i]=sv3[i];
    __syncthreads();

    int i = blockIdx.x*4 + wid;
    if (i >= 30) return;
    int k,r0,c0,g; sub_info(i,k,r0,c0,g);
    int kk=k*k;
    const float* Wv = s_sv + ((g==0)?0:(g==1)?100:(g==2)?325:725);
    if (lane<kk) s_gi[wid][lane]=(r0+lane/k)*5+(c0+lane%k);
    __syncwarp();
    for (int e=lane;e<kk*25;e+=32){
        int r=e/25, c=e%25;
        const float* crow=&s_cov[s_gi[wid][r]*25];
        float s=0.f;
        for (int jj=0;jj<kk;jj++) s += crow[s_gi[wid][jj]]*Wv[jj*25+c];
        s_G[wid][e]=s;
    }
    __syncwarp();
    for (int e=lane;e<625;e+=32){
        int a=e/25, bb=e%25;
        float s=0.f;
        for (int r=0;r<kk;r++) s += Wv[r*25+a]*s_G[wid][r*25+bb];
        if (a==bb) s += 4e-6f*(float)(a+1);
        s_C[wid][a*27+bb]=s;
    }
    __syncwarp();

    unsigned long long ap[13];
    float x = 0.f;
    if (lane < 25){
        #pragma unroll
        for (int j=0;j<12;j++) ap[j]=pk2(s_C[wid][(2*j)*27+lane], s_C[wid][(2*j+1)*27+lane]);
        ap[12]=pk2(s_C[wid][24*27+lane], 0.f);
        x = pnorm2<13>(ap);
    } else {
        #pragma unroll
        for (int j=0;j<13;j++) ap[j]=0ull;
    }

    hestenes_p<25>(ap, x, lane, 12);

    float xf = pnorm2<13>(ap);
    float wt = g_w[bt*30+i];
    float xs2 = fmaxf(xf, 1e-18f);
    float gsc = 0.5f*wt*__logf(xs2) / fmaxf(xf, 1e-30f);

    if (lane<25){
        #pragma unroll
        for (int j=0;j<12;j++){
            float lo,hi; upk2(ap[j],lo,hi);
            s_C[wid][(2*j)*27+lane]=lo;   s_C[wid][(2*j+1)*27+lane]=hi;
            s_G[wid][(2*j)*27+lane]=gsc*lo; s_G[wid][(2*j+1)*27+lane]=gsc*hi;
        }
        float lo,hi; upk2(ap[12],lo,hi);
        s_C[wid][24*27+lane]=lo;
        s_G[wid][24*27+lane]=gsc*lo;
    }
    __syncwarp();
    float* outp = g_logV + (bt*30+i)*625;
    for (int e=lane;e<325;e+=32){
        int r,c; tri25(e,r,c);
        float s=0.f;
        for (int m=0;m<25;m++) s += s_G[wid][r*27+m]*s_C[wid][c*27+m];
        outp[r*25+c]=s;
        if (r!=c) outp[c*25+r]=s;
    }
}

// ---------------- kernel 4c: sum + one-sided eigh + Rayleigh + exp/rect ----
__global__ __launch_bounds__(128) void k_s1fin(){
    __shared__ float s_L[675];   // lda 27, kept intact for Rayleigh
    __shared__ float s_C[675];
    __shared__ float s_G[675];

    int tid=threadIdx.x, lane=tid&31, wid=tid>>5;
    int bt=blockIdx.x;
    const float* base = g_logV + bt*30*625;
    for (int e=tid;e<625;e+=128){
        float s=0.f;
        for (int i=0;i<30;i++) s += base[i*625+e];
        int r=e/25,c=e%25;
        s_L[r*27+c]=s;
    }
    __syncthreads();
    if (wid==0){
        unsigned long long ap[13];
        float x=0.f;
        if (lane<25){
            #pragma unroll
            for (int j=0;j<12;j++) ap[j]=pk2(s_L[(2*j)*27+lane], s_L[(2*j+1)*27+lane]);
            ap[12]=pk2(s_L[24*27+lane], 0.f);
            x = pnorm2<13>(ap);
        } else {
            #pragma unroll
            for (int j=0;j<13;j++) ap[j]=0ull;
        }

        hestenes_p<25>(ap, x, lane, 12);

        float av[25];
        if (lane<25){
            #pragma unroll
            for (int j=0;j<12;j++) upk2(ap[j], av[2*j], av[2*j+1]);
            float hi_d; upk2(ap[12], av[24], hi_d);
        } else {
            #pragma unroll
            for (int j=0;j<25;j++) av[j]=0.f;
        }
        float xf = pnorm2<13>(ap);
        float num=0.f;
        if (lane<25){
            #pragma unroll 1
            for (int j=0;j<25;j++){
                float t=0.f;
                #pragma unroll
                for (int kx=0;kx<25;kx++) t += s_L[j*27+kx]*av[kx];
                num += av[j]*t;
            }
        }
        float lam = num / fmaxf(xf, 1e-30f);
        float mu = fmaxf(__expf(lam), 1e-4f);
        float coef = mu / fmaxf(xf, 1e-30f);
        if (lane<25){
            #pragma unroll
            for (int j=0;j<25;j++){
                s_C[j*27+lane]=av[j];
                s_G[j*27+lane]=coef*av[j];
            }
        }
    }
    __syncthreads();
    float* xo = g_xm + bt*625;
    for (int e=tid;e<325;e+=128){
        int r,c; tri25(e,r,c);
        float s=0.f;
        for (int m=0;m<25;m++) s += s_G[r*27+m]*s_C[c*27+m];
        xo[r*25+c]=s;
        if (r!=c) xo[c*25+r]=s;
    }
}

// ---------------- kernel 5: stage-2 attention + feat + linear ----------------
__global__ __launch_bounds__(128) void k_stage2(
    const float* __restrict__ mq,const float* __restrict__ mk,const float* __restrict__ mv,
    const float* __restrict__ lw,const float* __restrict__ lb,float* __restrict__ out)
{
    __shared__ float s_xm[1875];
    __shared__ float s_W[3][450];
    __shared__ float s_M[9][324];
    __shared__ float s_A[4][342];   // 18x18, lda 19
    __shared__ float s_U[4][342];
    __shared__ float s_tmp[4][450];
    __shared__ float s_norm[9];
    __shared__ float s_P[3][3];
    __shared__ float s_feat[513];

    int tid=threadIdx.x, lane=tid&31, wid=tid>>5;
    int b=blockIdx.x;
    for (int i=tid;i<1875;i+=128) s_xm[i]=g_xm[b*1875+i];
    for (int i=tid;i<450;i+=128){ s_W[0][i]=mq[i]; s_W[1][i]=mk[i]; s_W[2][i]=mv[i]; }
    __syncthreads();

    for (int task=wid; task<9; task+=4){
        int t=task/3, which=task%3;
        const float* X=&s_xm[t*625];
        const float* W=s_W[which];
        float* tmp=s_tmp[wid];
        for (int e=lane;e<450;e+=32){
            int r=e/18,c=e%18;
            float s=0.f;
            for (int j=0;j<25;j++) s += X[r*25+j]*W[j*18+c];
            tmp[e]=s;
        }
        __syncwarp();
        for (int e=lane;e<324;e+=32){
            int a=e/18,bb=e%18;
            float s=0.f;
            for (int r=0;r<25;r++) s += W[r*18+a]*tmp[r*18+bb];
            s_A[wid][a*19+bb]=s;
        }
        __syncwarp();
        unsigned long long ap[9];
        float x=0.f;
        if (lane<18){
            #pragma unroll
            for (int j=0;j<9;j++) ap[j]=pk2(s_A[wid][(2*j)*19+lane], s_A[wid][(2*j+1)*19+lane]);
            x = pnorm2<9>(ap);
        } else {
            #pragma unroll
            for (int j=0;j<9;j++) ap[j]=0ull;
        }

        hestenes_p<18>(ap, x, lane, 10);

        float xf = pnorm2<9>(ap);
        float lgl = 0.5f*__logf(fmaxf(xf,1e-18f));
        float gcf = lgl / fmaxf(xf,1e-30f);
        if (lane<18){
            #pragma unroll
            for (int j=0;j<9;j++){
                float lo,hi; upk2(ap[j],lo,hi);
                s_A[wid][(2*j)*19+lane]=lo;     s_A[wid][(2*j+1)*19+lane]=hi;
                s_U[wid][(2*j)*19+lane]=gcf*lo; s_U[wid][(2*j+1)*19+lane]=gcf*hi;
            }
        }
        __syncwarp();
        float nrm=0.f;
        for (int e=lane;e<171;e+=32){
            int r,c; tri18(e,r,c);
            float s=0.f;
            for (int m=0;m<18;m++) s += s_U[wid][r*19+m]*s_A[wid][c*19+m];
            s_M[task][r*18+c]=s;
            s_M[task][c*18+r]=s;
            nrm += (r==c) ? s*s : 2.f*s*s;
        }
        nrm=warp_sum(nrm);
        if (lane==0) s_norm[task]=nrm;
        __syncwarp();
    }
    __syncthreads();

    for (int pr=wid; pr<9; pr+=4){
        int i=pr/3, j=pr%3;
        const float* LK=s_M[i*3+1];
        const float* LQ=s_M[j*3+0];
        float cr=0.f;
        for (int e=lane;e<324;e+=32) cr += LK[e]*LQ[e];
        cr=warp_sum(cr);
        if (lane==0){
            float E=fmaxf(s_norm[i*3+1]+s_norm[j*3+0]-2.f*cr,0.f);
            s_P[i][j]=1.f/(1.f+log1pf(E));
        }
    }
    __syncthreads();
    if (tid==0){
        for (int j=0;j<3;j++){
            float m=fmaxf(fmaxf(s_P[0][j],s_P[1][j]),s_P[2][j]);
            float e0=expf(s_P[0][j]-m), e1=expf(s_P[1][j]-m), e2=expf(s_P[2][j]-m);
            float inv=1.f/(e0+e1+e2);
            s_P[0][j]=e0*inv; s_P[1][j]=e1*inv; s_P[2][j]=e2*inv;
        }
    }
    __syncthreads();

    // last 3: out_log >= ln(1e-4)*I -> A+10I PSD, shifted one-sided Jacobi
    if (wid<3){
        int j=wid;
        float p0=s_P[0][j], p1=s_P[1][j], p2=s_P[2][j];
        for (int e=lane;e<324;e+=32){
            int r=e/18,c=e%18;
            float v = p0*s_M[2][e]+p1*s_M[5][e]+p2*s_M[8][e];
            if (r==c) v += 10.f;
            s_A[wid][r*19+c]=v;
        }
        __syncwarp();
        unsigned long long ap[9];
        float x=0.f;
        if (lane<18){
            #pragma unroll
            for (int jj=0;jj<9;jj++) ap[jj]=pk2(s_A[wid][(2*jj)*19+lane], s_A[wid][(2*jj+1)*19+lane]);
            x = pnorm2<9>(ap);
        } else {
            #pragma unroll
            for (int jj=0;jj<9;jj++) ap[jj]=0ull;
        }

        hestenes_p<18>(ap, x, lane, 10);

        float xf = pnorm2<9>(ap);
        float lamp = sqrtf(fmaxf(xf,1e-30f));
        float lam  = fmaxf(lamp - 10.f, -9.2103403719761818f);
        float gcf  = lam / fmaxf(xf,1e-30f);
        if (lane<18){
            #pragma unroll
            for (int jj=0;jj<9;jj++){
                float lo,hi; upk2(ap[jj],lo,hi);
                s_A[wid][(2*jj)*19+lane]=lo;     s_A[wid][(2*jj+1)*19+lane]=hi;
                s_U[wid][(2*jj)*19+lane]=gcf*lo; s_U[wid][(2*jj+1)*19+lane]=gcf*hi;
            }
        }
        __syncwarp();
        for (int e=lane;e<171;e+=32){
            int r,c; tri18(e,r,c);
            float s=0.f;
            for (int m=0;m<18;m++) s += s_U[wid][r*19+m]*s_A[wid][c*19+m];
            float coef=(r==c)?1.f:1.41421356237309515f;
            int p = r*18 - (r*(r-1))/2 + (c-r);
            s_feat[j*171+p]=coef*s;
        }
    }
    __syncthreads();

    {
        int o=wid;
        float s=0.f;
        for (int f=lane;f<513;f+=32) s += s_feat[f]*lw[o*513+f];
        s=warp_sum(s);
        if (lane==0) out[b*4+o]=s+lb[o];
    }
}

extern "C" void kernel_launch(void* const* d_in, const int* in_sizes, int n_in,
                              void* d_out, int out_size) {
    const float* x    = (const float*)d_in[0];
    const float* c1w  = (const float*)d_in[1];
    const float* c1b  = (const float*)d_in[2];
    const float* bn1g = (const float*)d_in[3];
    const float* bn1b = (const float*)d_in[4];
    const float* bn1m = (const float*)d_in[5];
    const float* bn1v = (const float*)d_in[6];
    const float* c2w  = (const float*)d_in[7];
    const float* c2b  = (const float*)d_in[8];
    const float* bn2g = (const float*)d_in[9];
    const float* bn2b = (const float*)d_in[10];
    const float* bn2m = (const float*)d_in[11];
    const float* bn2v = (const float*)d_in[12];

    const float *sq[4], *sk[4], *sv[4];
    if (in_sizes[13]==16 && in_sizes[14]==16 && in_sizes[15]==100){
        for (int i=0;i<4;i++){
            sq[i] = (const float*)d_in[13+3*i];
            sk[i] = (const float*)d_in[14+3*i];
            sv[i] = (const float*)d_in[15+3*i];
        }
    } else {
        for (int i=0;i<4;i++){
            sq[i] = (const float*)d_in[13+i];
            sk[i] = (const float*)d_in[17+i];
            sv[i] = (const float*)d_in[21+i];
        }
    }
    const float* mq   = (const float*)d_in[25];
    const float* mk   = (const float*)d_in[26];
    const float* mv   = (const float*)d_in[27];
    const float* lw   = (const float*)d_in[28];
    const float* lb   = (const float*)d_in[29];
    float* out = (float*)d_out;

    k_prep<<<1,256>>>(c1w,c1b,bn1g,bn1b,bn1m,bn1v,c2w,c2b,bn2g,bn2b,bn2m,bn2v);
    k_conv1<<<dim3(8,NB),128>>>(x);
    k_conv2<<<dim3(4,NB),128>>>();
    k_cov<<<dim3(3,NB),256>>>();
    k_wts<<<dim3(3,NB),256>>>(sq[3],sk[0],sk[1],sk[2],sk[3]);
    k_veigh<<<dim3(8,3,NB),128>>>(sv[0],sv[1],sv[2],sv[3]);
    k_s1fin<<<3*NB,128>>>();
    k_stage2<<<NB,128>>>(mq,mk,mv,lw,lb,out);
}